// round 14
// baseline (speedup 1.0000x reference)
#include <cuda_runtime.h>
#include <cuda_fp16.h>
#include <cstring>

#define S 128
#define H 64
#define LDH 72     // leading dim (halves) for h1 tiles; 144 B = 9*16B granules -> ldmatrix conflict-free

// Dynamic shared memory layout (bytes):
//   [0, 18432)      h1_hi half[128*LDH]
//   [18432, 36864)  h1_lo half[128*LDH]
//   [36864, 36880)  sWprod float[4]
//   [36880, 36928)  sSum  float[4][3]
#define SMEM_BYTES 36928

// W2 / heads-B' pre-packed DIRECTLY in mma.m16n8k16 B-fragment register layout.
// Index: [kt*8+nt][lane] (uint2 = {b0,b1}), lane q=lane&3,g=lane>>2:
//   b0 = {B[kt*16+2q][nt*8+g], B[kt*16+2q+1][nt*8+g]}, b1 = rows +8.
__device__ __align__(16) uint2 gFW2hi[4 * 8 * 32];   // 8 KB
__device__ __align__(16) uint2 gFW2lo[4 * 8 * 32];
__device__ __align__(16) uint2 gFBphi[4 * 32];       // heads B' = [Wsig|Wrgb|0...], N=8
__device__ __align__(16) uint2 gFBplo[4 * 32];

__device__ __forceinline__ unsigned pack2(float a, float b, bool lo) {
    const __half ha = __float2half_rn(a);
    const __half hb = __float2half_rn(b);
    __half2 h;
    if (!lo) h = __halves2half2(ha, hb);
    else     h = __halves2half2(__float2half_rn(a - __half2float(ha)),
                                __float2half_rn(b - __half2float(hb)));
    unsigned u; memcpy(&u, &h, 4); return u;
}

__global__ void pack_kernel(const float* __restrict__ W2,
                            const float* __restrict__ Wsig,
                            const float* __restrict__ Wrgb)
{
    const int i = blockIdx.x * blockDim.x + threadIdx.x;
    if (i < 4 * 8 * 32) {
        const int lane = i & 31, nt = (i >> 5) & 7, kt = i >> 8;
        const int q = lane & 3, g = lane >> 2;
        const int k0 = kt * 16 + 2 * q;
        const int j  = nt * 8 + g;
        const float w00 = W2[(k0 + 0) * H + j];
        const float w01 = W2[(k0 + 1) * H + j];
        const float w10 = W2[(k0 + 8) * H + j];
        const float w11 = W2[(k0 + 9) * H + j];
        gFW2hi[i] = make_uint2(pack2(w00, w01, false), pack2(w10, w11, false));
        gFW2lo[i] = make_uint2(pack2(w00, w01, true),  pack2(w10, w11, true));
    }
    if (i < 4 * 32) {
        const int lane = i & 31, ntp = i >> 5;
        const int q = lane & 3, g = lane >> 2;
        const int k0 = ntp * 16 + 2 * q;
        auto bp = [&](int k, int n) -> float {
            if (n == 0) return Wsig[k];
            if (n <= 3) return Wrgb[k * 3 + (n - 1)];
            return 0.0f;
        };
        const float w00 = bp(k0 + 0, g), w01 = bp(k0 + 1, g);
        const float w10 = bp(k0 + 8, g), w11 = bp(k0 + 9, g);
        gFBphi[i] = make_uint2(pack2(w00, w01, false), pack2(w10, w11, false));
        gFBplo[i] = make_uint2(pack2(w00, w01, true),  pack2(w10, w11, true));
    }
}

__device__ __forceinline__ void ldsm_x4(unsigned& r0, unsigned& r1, unsigned& r2, unsigned& r3, unsigned a) {
    asm volatile("ldmatrix.sync.aligned.m8n8.x4.shared.b16 {%0,%1,%2,%3}, [%4];"
                 : "=r"(r0), "=r"(r1), "=r"(r2), "=r"(r3) : "r"(a));
}
__device__ __forceinline__ void mma16816(float* d, unsigned a0, unsigned a1, unsigned a2, unsigned a3,
                                         unsigned b0, unsigned b1) {
    asm volatile("mma.sync.aligned.m16n8k16.row.col.f32.f16.f16.f32 "
                 "{%0,%1,%2,%3},{%4,%5,%6,%7},{%8,%9},{%0,%1,%2,%3};"
                 : "+f"(d[0]), "+f"(d[1]), "+f"(d[2]), "+f"(d[3])
                 : "r"(a0), "r"(a1), "r"(a2), "r"(a3), "r"(b0), "r"(b1));
}
__device__ __forceinline__ unsigned h2u(__half2 h) { unsigned u; memcpy(&u, &h, 4); return u; }

__global__ __launch_bounds__(128, 5)
void render_kernel(const float* __restrict__ rays_o,
                   const float* __restrict__ rays_d,
                   const float* __restrict__ nearv,
                   const float* __restrict__ farv,
                   const float* __restrict__ jitter,
                   const float* __restrict__ density,
                   const float* __restrict__ W1,
                   const float* __restrict__ b1,
                   const float* __restrict__ b2,
                   const float* __restrict__ bsig,
                   const float* __restrict__ brgb,
                   float* __restrict__ out)
{
    extern __shared__ __align__(16) char smem[];
    __half* hH1hi = reinterpret_cast<__half*>(smem);
    __half* hH1lo = reinterpret_cast<__half*>(smem + 18432);
    float*  sWprod = reinterpret_cast<float*>(smem + 36864);   // [4]
    float*  sSum   = reinterpret_cast<float*>(smem + 36880);   // [4][3]

    const int t    = threadIdx.x;     // 0..127, sample index
    const int lane = t & 31;
    const int warp = t >> 5;          // 0..3
    const int ray  = blockIdx.x;

    // ---- per-sample ray setup + occupancy-grid mask ----
    const float ox = rays_o[ray * 3 + 0];
    const float oy = rays_o[ray * 3 + 1];
    const float oz = rays_o[ray * 3 + 2];
    const float dx = rays_d[ray * 3 + 0];
    const float dy = rays_d[ray * 3 + 1];
    const float dz = rays_d[ray * 3 + 2];
    const float nr = nearv[ray];
    const float fr = farv[ray];
    const float step = (fr - nr) * (1.0f / (float)S);
    const float z = nr + (float)t * step;

    const float p0x = ox + z * dx;
    const float p0y = oy + z * dy;
    const float p0z = oz + z * dz;
    const float ux = (p0x - (-1.25f)) / 2.5f;
    const float uy = (p0y - (-1.55f)) / 2.5f;
    const float uz = (p0z - (-1.25f)) / 2.5f;
    const int ix = (int)floorf(ux * 64.0f);
    const int iy = (int)floorf(uy * 64.0f);
    const int iz = (int)floorf(uz * 64.0f);
    const bool inb = (ix >= 0) & (ix < 64) & (iy >= 0) & (iy < 64) & (iz >= 0) & (iz < 64);
    const int cx = min(max(ix, 0), 63);
    const int cy = min(max(iy, 0), 63);
    const int cz = min(max(iz, 0), 63);
    const bool occ = density[(cx * 64 + cy) * 64 + cz] > 0.5f;
    const bool mask = occ && inb;

    const int any_active = __syncthreads_or(mask ? 1 : 0);     // barrier 1
    if (!any_active) {
        if (t == 0) {
            out[ray * 3 + 0] = 1.0f;
            out[ray * 3 + 1] = 1.0f;
            out[ray * 3 + 2] = 1.0f;
        }
        return;
    }

    const unsigned wball = __ballot_sync(0xffffffffu, mask);
    const bool warp_active = (wball != 0u);

    const float zv = mask ? z : 0.0f;
    const float zj = zv + jitter[ray * S + t] * step;
    const float px = ox + zj * dx;
    const float py = oy + zj * dy;
    const float pz = oz + zj * dz;

    // ---- layer 1 (scalar fp32, K=3): float4 weight loads, 128-bit h1 stores ----
    if (warp_active) {
        uint4* hrowHi = reinterpret_cast<uint4*>(hH1hi + t * LDH);
        uint4* hrowLo = reinterpret_cast<uint4*>(hH1lo + t * LDH);
        #pragma unroll
        for (int j8 = 0; j8 < H; j8 += 8) {
            const float4 wx0 = *reinterpret_cast<const float4*>(W1 + j8);
            const float4 wx1 = *reinterpret_cast<const float4*>(W1 + j8 + 4);
            const float4 wy0 = *reinterpret_cast<const float4*>(W1 + H + j8);
            const float4 wy1 = *reinterpret_cast<const float4*>(W1 + H + j8 + 4);
            const float4 wz0 = *reinterpret_cast<const float4*>(W1 + 2 * H + j8);
            const float4 wz1 = *reinterpret_cast<const float4*>(W1 + 2 * H + j8 + 4);
            const float4 bb0 = *reinterpret_cast<const float4*>(b1 + j8);
            const float4 bb1 = *reinterpret_cast<const float4*>(b1 + j8 + 4);
            float vj[8];
            vj[0] = fmaxf(fmaf(px, wx0.x, fmaf(py, wy0.x, fmaf(pz, wz0.x, bb0.x))), 0.0f);
            vj[1] = fmaxf(fmaf(px, wx0.y, fmaf(py, wy0.y, fmaf(pz, wz0.y, bb0.y))), 0.0f);
            vj[2] = fmaxf(fmaf(px, wx0.z, fmaf(py, wy0.z, fmaf(pz, wz0.z, bb0.z))), 0.0f);
            vj[3] = fmaxf(fmaf(px, wx0.w, fmaf(py, wy0.w, fmaf(pz, wz0.w, bb0.w))), 0.0f);
            vj[4] = fmaxf(fmaf(px, wx1.x, fmaf(py, wy1.x, fmaf(pz, wz1.x, bb1.x))), 0.0f);
            vj[5] = fmaxf(fmaf(px, wx1.y, fmaf(py, wy1.y, fmaf(pz, wz1.y, bb1.y))), 0.0f);
            vj[6] = fmaxf(fmaf(px, wx1.z, fmaf(py, wy1.z, fmaf(pz, wz1.z, bb1.z))), 0.0f);
            vj[7] = fmaxf(fmaf(px, wx1.w, fmaf(py, wy1.w, fmaf(pz, wz1.w, bb1.w))), 0.0f);

            uint4 vhi, vlo;
            __half2* phi = reinterpret_cast<__half2*>(&vhi);
            __half2* plo = reinterpret_cast<__half2*>(&vlo);
            #pragma unroll
            for (int u = 0; u < 4; u++) {
                const float v0 = vj[2 * u], v1 = vj[2 * u + 1];
                const __half h0 = __float2half_rn(v0);
                const __half h1 = __float2half_rn(v1);
                phi[u] = __halves2half2(h0, h1);
                plo[u] = __halves2half2(__float2half_rn(v0 - __half2float(h0)),
                                        __float2half_rn(v1 - __half2float(h1)));
            }
            hrowHi[j8 >> 3] = vhi;
            hrowLo[j8 >> 3] = vlo;
        }
    }
    __syncthreads();   // barrier 2: h1 staged

    const unsigned h1hiU = (unsigned)__cvta_generic_to_shared(hH1hi);
    const unsigned h1loU = (unsigned)__cvta_generic_to_shared(hH1lo);

    const int q = lane & 3;

    float hc[2][4];                       // heads C' (sigma,r | g,b logits)
    #pragma unroll
    for (int mt = 0; mt < 2; mt++)
        #pragma unroll
        for (int u = 0; u < 4; u++) hc[mt][u] = 0.0f;

    if (warp_active) {
        const int arow = lane & 15;
        const int acol = (lane >> 4) * 8;

        // Two N-halves: compute C for nt in [4h, 4h+4), then immediately run
        // that half's heads MMAs so only 16 accumulators are live at a time.
        #pragma unroll
        for (int h = 0; h < 2; h++) {
            float C[2][4][4];             // half-width h2 accumulators
            #pragma unroll
            for (int mt = 0; mt < 2; mt++)
                #pragma unroll
                for (int n4 = 0; n4 < 4; n4++)
                    #pragma unroll
                    for (int u = 0; u < 4; u++) C[mt][n4][u] = 0.0f;

            #pragma unroll
            for (int k = 0; k < 4; k++) {
                unsigned aHi[2][4], aLo[2][4];
                #pragma unroll
                for (int mt = 0; mt < 2; mt++) {
                    const unsigned off = (unsigned)(((warp * 32 + mt * 16 + arow) * LDH + k * 16 + acol) * 2);
                    ldsm_x4(aHi[mt][0], aHi[mt][1], aHi[mt][2], aHi[mt][3], h1hiU + off);
                    ldsm_x4(aLo[mt][0], aLo[mt][1], aLo[mt][2], aLo[mt][3], h1loU + off);
                }
                #pragma unroll
                for (int n4 = 0; n4 < 4; n4++) {
                    const int nt = h * 4 + n4;
                    const uint2 bh = gFW2hi[(k * 8 + nt) * 32 + lane];
                    const uint2 bl = gFW2lo[(k * 8 + nt) * 32 + lane];
                    #pragma unroll
                    for (int mt = 0; mt < 2; mt++) {
                        mma16816(C[mt][n4], aHi[mt][0], aHi[mt][1], aHi[mt][2], aHi[mt][3], bh.x, bh.y);
                        mma16816(C[mt][n4], aHi[mt][0], aHi[mt][1], aHi[mt][2], aHi[mt][3], bl.x, bl.y);
                        mma16816(C[mt][n4], aLo[mt][0], aLo[mt][1], aLo[mt][2], aLo[mt][3], bh.x, bh.y);
                    }
                }
            }

            // ---- heads for this half: relu(h2 + b2) @ [Wsig|Wrgb] ----
            #pragma unroll
            for (int j = 0; j < 2; j++) {
                const int ntp = h * 2 + j;
                const uint2 bph = gFBphi[ntp * 32 + lane];
                const uint2 bpl = gFBplo[ntp * 32 + lane];
                const float2 bb0 = *reinterpret_cast<const float2*>(b2 + (2 * ntp) * 8 + 2 * q);
                const float2 bb1 = *reinterpret_cast<const float2*>(b2 + (2 * ntp + 1) * 8 + 2 * q);
                #pragma unroll
                for (int mt = 0; mt < 2; mt++) {
                    unsigned aH[4], aL[4];
                    #pragma unroll
                    for (int sub = 0; sub < 2; sub++) {
                        const float* c = C[mt][2 * j + sub];
                        const float2 bb = sub ? bb1 : bb0;
                        const float v0 = fmaxf(c[0] + bb.x, 0.0f);
                        const float v1 = fmaxf(c[1] + bb.y, 0.0f);
                        const float v2 = fmaxf(c[2] + bb.x, 0.0f);
                        const float v3 = fmaxf(c[3] + bb.y, 0.0f);
                        const __half2 h01 = __floats2half2_rn(v0, v1);
                        const __half2 h23 = __floats2half2_rn(v2, v3);
                        aH[2 * sub + 0] = h2u(h01);
                        aH[2 * sub + 1] = h2u(h23);
                        aL[2 * sub + 0] = h2u(__floats2half2_rn(v0 - __low2float(h01), v1 - __high2float(h01)));
                        aL[2 * sub + 1] = h2u(__floats2half2_rn(v2 - __low2float(h23), v3 - __high2float(h23)));
                    }
                    mma16816(hc[mt], aH[0], aH[1], aH[2], aH[3], bph.x, bph.y);
                    mma16816(hc[mt], aH[0], aH[1], aH[2], aH[3], bpl.x, bpl.y);
                    mma16816(hc[mt], aL[0], aL[1], aL[2], aL[3], bph.x, bph.y);
                }
            }
        }
    }

    // ---- intra-warp redistribution of head logits (no smem, no barrier) ----
    const int mt_t   = lane >> 4;
    const int half_t = (lane >> 3) & 1;
    const int src0   = (lane & 7) * 4;
    float sigL = 0.0f, crL = 0.0f, cgL = 0.0f, cbL = 0.0f;
    #pragma unroll
    for (int mt = 0; mt < 2; mt++) {
        #pragma unroll
        for (int hf = 0; hf < 2; hf++) {
            const float v00 = __shfl_sync(0xffffffffu, hc[mt][hf * 2 + 0], src0);
            const float v01 = __shfl_sync(0xffffffffu, hc[mt][hf * 2 + 1], src0);
            const float v10 = __shfl_sync(0xffffffffu, hc[mt][hf * 2 + 0], src0 + 1);
            const float v11 = __shfl_sync(0xffffffffu, hc[mt][hf * 2 + 1], src0 + 1);
            if (mt == mt_t && hf == half_t) { sigL = v00; crL = v01; cgL = v10; cbL = v11; }
        }
    }

    // ---- per-sample nonlinearities ----
    float alpha = 0.0f, r = 0.0f, gg = 0.0f, b = 0.0f;
    if (mask) {
        const float sigma = sigL + bsig[0];
        const float tau = fmaxf(sigma, 0.0f) * step;
        alpha = 1.0f - __expf(-tau);
        r  = 1.0f / (1.0f + __expf(-(crL + brgb[0])));
        gg = 1.0f / (1.0f + __expf(-(cgL + brgb[1])));
        b  = 1.0f / (1.0f + __expf(-(cbL + brgb[2])));
    }

    // ---- composite: warp scan; pre-factors applied at combine (1 barrier) ----
    const float f = 1.0f - alpha + 1e-10f;
    float incl = f;
    #pragma unroll
    for (int off = 1; off < 32; off <<= 1) {
        const float v = __shfl_up_sync(0xffffffffu, incl, off);
        if (lane >= off) incl *= v;
    }
    const float wtot = __shfl_sync(0xffffffffu, incl, 31);
    float excl = __shfl_up_sync(0xffffffffu, incl, 1);
    if (lane == 0) excl = 1.0f;

    const float w = alpha * excl;    // warp-prefix `pre` applied at combine
    float wr = w * r, wg = w * gg, wb = w * b;
    #pragma unroll
    for (int off = 16; off > 0; off >>= 1) {
        wr += __shfl_down_sync(0xffffffffu, wr, off);
        wg += __shfl_down_sync(0xffffffffu, wg, off);
        wb += __shfl_down_sync(0xffffffffu, wb, off);
    }
    if (lane == 0) {
        sWprod[warp] = wtot;
        sSum[warp * 3 + 0] = wr;
        sSum[warp * 3 + 1] = wg;
        sSum[warp * 3 + 2] = wb;
    }
    __syncthreads();   // barrier 3

    if (t == 0) {
        const float p1 = sWprod[0];
        const float p2 = p1 * sWprod[1];
        const float p3 = p2 * sWprod[2];
        const float no_hit = p3 * sWprod[3];
        out[ray * 3 + 0] = no_hit + sSum[0] + p1 * sSum[3] + p2 * sSum[6] + p3 * sSum[9];
        out[ray * 3 + 1] = no_hit + sSum[1] + p1 * sSum[4] + p2 * sSum[7] + p3 * sSum[10];
        out[ray * 3 + 2] = no_hit + sSum[2] + p1 * sSum[5] + p2 * sSum[8] + p3 * sSum[11];
    }
}

extern "C" void kernel_launch(void* const* d_in, const int* in_sizes, int n_in,
                              void* d_out, int out_size)
{
    const float* rays_o  = (const float*)d_in[0];
    const float* rays_d  = (const float*)d_in[1];
    const float* nearv   = (const float*)d_in[2];
    const float* farv    = (const float*)d_in[3];
    const float* jitter  = (const float*)d_in[4];
    const float* density = (const float*)d_in[5];
    const float* W1      = (const float*)d_in[6];
    const float* b1      = (const float*)d_in[7];
    const float* W2      = (const float*)d_in[8];
    const float* b2      = (const float*)d_in[9];
    const float* Wsig    = (const float*)d_in[10];
    const float* bsig    = (const float*)d_in[11];
    const float* Wrgb    = (const float*)d_in[12];
    const float* brgb    = (const float*)d_in[13];

    const int n_rays = in_sizes[2];   // near has one entry per ray

    cudaFuncSetAttribute(render_kernel, cudaFuncAttributeMaxDynamicSharedMemorySize, SMEM_BYTES);

    pack_kernel<<<8, 128>>>(W2, Wsig, Wrgb);
    render_kernel<<<n_rays, 128, SMEM_BYTES>>>(rays_o, rays_d, nearv, farv, jitter, density,
                                               W1, b1, b2, bsig, brgb,
                                               (float*)d_out);
}

// round 16
// speedup vs baseline: 1.2659x; 1.2659x over previous
#include <cuda_runtime.h>
#include <cuda_fp16.h>
#include <cstring>

#define S 128
#define H 64

// W2 / heads-B' pre-packed DIRECTLY in mma.m16n8k16 B-fragment register layout.
// Index: [kt*8+nt][lane] (uint2 = {b0,b1}), lane q=lane&3,g=lane>>2:
//   b0 = {B[kt*16+2q][nt*8+g], B[kt*16+2q+1][nt*8+g]}, b1 = rows +8.
__device__ __align__(16) uint2 gFW2hi[4 * 8 * 32];   // 8 KB
__device__ __align__(16) uint2 gFW2lo[4 * 8 * 32];
__device__ __align__(16) uint2 gFBphi[4 * 32];       // heads B' = [Wsig|Wrgb|0...], N=8
__device__ __align__(16) uint2 gFBplo[4 * 32];

__device__ __forceinline__ unsigned pack2(float a, float b, bool lo) {
    const __half ha = __float2half_rn(a);
    const __half hb = __float2half_rn(b);
    __half2 h;
    if (!lo) h = __halves2half2(ha, hb);
    else     h = __halves2half2(__float2half_rn(a - __half2float(ha)),
                                __float2half_rn(b - __half2float(hb)));
    unsigned u; memcpy(&u, &h, 4); return u;
}

__global__ void pack_kernel(const float* __restrict__ W2,
                            const float* __restrict__ Wsig,
                            const float* __restrict__ Wrgb)
{
    const int i = blockIdx.x * blockDim.x + threadIdx.x;
    if (i < 4 * 8 * 32) {
        const int lane = i & 31, nt = (i >> 5) & 7, kt = i >> 8;
        const int q = lane & 3, g = lane >> 2;
        const int k0 = kt * 16 + 2 * q;
        const int j  = nt * 8 + g;
        const float w00 = W2[(k0 + 0) * H + j];
        const float w01 = W2[(k0 + 1) * H + j];
        const float w10 = W2[(k0 + 8) * H + j];
        const float w11 = W2[(k0 + 9) * H + j];
        gFW2hi[i] = make_uint2(pack2(w00, w01, false), pack2(w10, w11, false));
        gFW2lo[i] = make_uint2(pack2(w00, w01, true),  pack2(w10, w11, true));
    }
    if (i < 4 * 32) {
        const int lane = i & 31, ntp = i >> 5;
        const int q = lane & 3, g = lane >> 2;
        const int k0 = ntp * 16 + 2 * q;
        auto bp = [&](int k, int n) -> float {
            if (n == 0) return Wsig[k];
            if (n <= 3) return Wrgb[k * 3 + (n - 1)];
            return 0.0f;
        };
        const float w00 = bp(k0 + 0, g), w01 = bp(k0 + 1, g);
        const float w10 = bp(k0 + 8, g), w11 = bp(k0 + 9, g);
        gFBphi[i] = make_uint2(pack2(w00, w01, false), pack2(w10, w11, false));
        gFBplo[i] = make_uint2(pack2(w00, w01, true),  pack2(w10, w11, true));
    }
}

__device__ __forceinline__ void mma16816(float* d, unsigned a0, unsigned a1, unsigned a2, unsigned a3,
                                         unsigned b0, unsigned b1) {
    asm volatile("mma.sync.aligned.m16n8k16.row.col.f32.f16.f16.f32 "
                 "{%0,%1,%2,%3},{%4,%5,%6,%7},{%8,%9},{%0,%1,%2,%3};"
                 : "+f"(d[0]), "+f"(d[1]), "+f"(d[2]), "+f"(d[3])
                 : "r"(a0), "r"(a1), "r"(a2), "r"(a3), "r"(b0), "r"(b1));
}
__device__ __forceinline__ unsigned h2u(__half2 h) { unsigned u; memcpy(&u, &h, 4); return u; }

__global__ __launch_bounds__(128, 4)
void render_kernel(const float* __restrict__ rays_o,
                   const float* __restrict__ rays_d,
                   const float* __restrict__ nearv,
                   const float* __restrict__ farv,
                   const float* __restrict__ jitter,
                   const float* __restrict__ density,
                   const float* __restrict__ W1,
                   const float* __restrict__ b1,
                   const float* __restrict__ b2,
                   const float* __restrict__ bsig,
                   const float* __restrict__ brgb,
                   float* __restrict__ out)
{
    __shared__ float sWprod[4];
    __shared__ float sSum[4][3];

    const int t    = threadIdx.x;     // 0..127, sample index
    const int lane = t & 31;
    const int warp = t >> 5;          // 0..3
    const int ray  = blockIdx.x;

    // ---- per-sample ray setup + occupancy-grid mask ----
    const float ox = rays_o[ray * 3 + 0];
    const float oy = rays_o[ray * 3 + 1];
    const float oz = rays_o[ray * 3 + 2];
    const float dx = rays_d[ray * 3 + 0];
    const float dy = rays_d[ray * 3 + 1];
    const float dz = rays_d[ray * 3 + 2];
    const float nr = nearv[ray];
    const float fr = farv[ray];
    const float step = (fr - nr) * (1.0f / (float)S);
    const float z = nr + (float)t * step;

    const float p0x = ox + z * dx;
    const float p0y = oy + z * dy;
    const float p0z = oz + z * dz;
    const float ux = (p0x - (-1.25f)) / 2.5f;
    const float uy = (p0y - (-1.55f)) / 2.5f;
    const float uz = (p0z - (-1.25f)) / 2.5f;
    const int ix = (int)floorf(ux * 64.0f);
    const int iy = (int)floorf(uy * 64.0f);
    const int iz = (int)floorf(uz * 64.0f);
    const bool inb = (ix >= 0) & (ix < 64) & (iy >= 0) & (iy < 64) & (iz >= 0) & (iz < 64);
    const int cx = min(max(ix, 0), 63);
    const int cy = min(max(iy, 0), 63);
    const int cz = min(max(iz, 0), 63);
    const bool occ = density[(cx * 64 + cy) * 64 + cz] > 0.5f;
    const bool mask = occ && inb;

    const int any_active = __syncthreads_or(mask ? 1 : 0);     // barrier 1
    if (!any_active) {
        if (t == 0) {
            out[ray * 3 + 0] = 1.0f;
            out[ray * 3 + 1] = 1.0f;
            out[ray * 3 + 2] = 1.0f;
        }
        return;
    }

    const unsigned wball = __ballot_sync(0xffffffffu, mask);
    const bool warp_active = (wball != 0u);

    const float zv = mask ? z : 0.0f;
    const float zj = zv + jitter[ray * S + t] * step;
    const float px = ox + zj * dx;
    const float py = oy + zj * dy;
    const float pz = oz + zj * dz;

    const int q = lane & 3;
    const int g = lane >> 2;

    float hc[2][4];                       // heads C' (sigma,r | g,b logits)
    #pragma unroll
    for (int mt = 0; mt < 2; mt++)
        #pragma unroll
        for (int u = 0; u < 4; u++) hc[mt][u] = 0.0f;

    if (warp_active) {
        // ---- fetch positions of the 4 sample rows this thread's fragments cover ----
        // local rows: g (mt0,a0/a2), g+8 (mt0,a1/a3), g+16 (mt1,a0/a2), g+24 (mt1,a1/a3)
        float rpx[4], rpy[4], rpz[4];
        #pragma unroll
        for (int i = 0; i < 4; i++) {
            const int src = g + i * 8;
            rpx[i] = __shfl_sync(0xffffffffu, px, src);
            rpy[i] = __shfl_sync(0xffffffffu, py, src);
            rpz[i] = __shfl_sync(0xffffffffu, pz, src);
        }

        float C[2][8][4];                 // h2 accumulators, register-resident
        #pragma unroll
        for (int mt = 0; mt < 2; mt++)
            #pragma unroll
            for (int nt = 0; nt < 8; nt++)
                #pragma unroll
                for (int u = 0; u < 4; u++) C[mt][nt][u] = 0.0f;

        #pragma unroll
        for (int k = 0; k < 4; k++) {
            // ---- layer 1 directly into A-fragment registers (no smem) ----
            // cols for this k-tile: c0=k*16+2q, c0+1, c0+8, c0+9
            unsigned aHi[2][4], aLo[2][4];
            {
                const int c0 = k * 16 + 2 * q;
                float v[4][4];   // [row i][col u: c0,c0+1,c0+8,c0+9]
                #pragma unroll
                for (int u = 0; u < 4; u++) {
                    const int cc = c0 + (u >> 1) * 8 + (u & 1);
                    const float wx = W1[cc];
                    const float wy = W1[H + cc];
                    const float wz = W1[2 * H + cc];
                    const float bb = b1[cc];
                    #pragma unroll
                    for (int i = 0; i < 4; i++)
                        v[i][u] = fmaxf(fmaf(rpx[i], wx, fmaf(rpy[i], wy, fmaf(rpz[i], wz, bb))), 0.0f);
                }
                #pragma unroll
                for (int mt = 0; mt < 2; mt++) {
                    const int i0 = mt * 2;       // row g (+16*mt)
                    const int i1 = mt * 2 + 1;   // row g+8 (+16*mt)
                    // a0={v[i0][c0],v[i0][c0+1]}, a1={v[i1][c0],v[i1][c0+1]},
                    // a2={v[i0][c0+8],v[i0][c0+9]}, a3={v[i1][c0+8],v[i1][c0+9]}
                    const __half2 h00 = __floats2half2_rn(v[i0][0], v[i0][1]);
                    const __half2 h10 = __floats2half2_rn(v[i1][0], v[i1][1]);
                    const __half2 h01 = __floats2half2_rn(v[i0][2], v[i0][3]);
                    const __half2 h11 = __floats2half2_rn(v[i1][2], v[i1][3]);
                    aHi[mt][0] = h2u(h00);
                    aHi[mt][1] = h2u(h10);
                    aHi[mt][2] = h2u(h01);
                    aHi[mt][3] = h2u(h11);
                    aLo[mt][0] = h2u(__floats2half2_rn(v[i0][0] - __low2float(h00), v[i0][1] - __high2float(h00)));
                    aLo[mt][1] = h2u(__floats2half2_rn(v[i1][0] - __low2float(h10), v[i1][1] - __high2float(h10)));
                    aLo[mt][2] = h2u(__floats2half2_rn(v[i0][2] - __low2float(h01), v[i0][3] - __high2float(h01)));
                    aLo[mt][3] = h2u(__floats2half2_rn(v[i1][2] - __low2float(h11), v[i1][3] - __high2float(h11)));
                }
            }
            #pragma unroll
            for (int nt = 0; nt < 8; nt++) {
                // B fragments: coalesced 8-byte loads from pre-packed global (L1-hot)
                const uint2 bh = gFW2hi[(k * 8 + nt) * 32 + lane];
                const uint2 bl = gFW2lo[(k * 8 + nt) * 32 + lane];
                #pragma unroll
                for (int mt = 0; mt < 2; mt++) {
                    mma16816(C[mt][nt], aHi[mt][0], aHi[mt][1], aHi[mt][2], aHi[mt][3], bh.x, bh.y);
                    mma16816(C[mt][nt], aHi[mt][0], aHi[mt][1], aHi[mt][2], aHi[mt][3], bl.x, bl.y);
                    mma16816(C[mt][nt], aLo[mt][0], aLo[mt][1], aLo[mt][2], aLo[mt][3], bh.x, bh.y);
                }
            }
        }

        // ---- heads: relu(h2 + b2) @ [Wsig|Wrgb], A' packed from C in registers ----
        #pragma unroll
        for (int ntp = 0; ntp < 4; ntp++) {
            const uint2 bph = gFBphi[ntp * 32 + lane];
            const uint2 bpl = gFBplo[ntp * 32 + lane];
            const float2 bb0 = *reinterpret_cast<const float2*>(b2 + (2 * ntp) * 8 + 2 * q);
            const float2 bb1 = *reinterpret_cast<const float2*>(b2 + (2 * ntp + 1) * 8 + 2 * q);
            #pragma unroll
            for (int mt = 0; mt < 2; mt++) {
                unsigned aH[4], aL[4];
                #pragma unroll
                for (int sub = 0; sub < 2; sub++) {
                    const float* c = C[mt][2 * ntp + sub];
                    const float2 bb = sub ? bb1 : bb0;
                    const float v0 = fmaxf(c[0] + bb.x, 0.0f);
                    const float v1 = fmaxf(c[1] + bb.y, 0.0f);
                    const float v2 = fmaxf(c[2] + bb.x, 0.0f);
                    const float v3 = fmaxf(c[3] + bb.y, 0.0f);
                    const __half2 h01 = __floats2half2_rn(v0, v1);
                    const __half2 h23 = __floats2half2_rn(v2, v3);
                    aH[2 * sub + 0] = h2u(h01);
                    aH[2 * sub + 1] = h2u(h23);
                    aL[2 * sub + 0] = h2u(__floats2half2_rn(v0 - __low2float(h01), v1 - __high2float(h01)));
                    aL[2 * sub + 1] = h2u(__floats2half2_rn(v2 - __low2float(h23), v3 - __high2float(h23)));
                }
                mma16816(hc[mt], aH[0], aH[1], aH[2], aH[3], bph.x, bph.y);
                mma16816(hc[mt], aH[0], aH[1], aH[2], aH[3], bpl.x, bpl.y);
                mma16816(hc[mt], aL[0], aL[1], aL[2], aL[3], bph.x, bph.y);
            }
        }
    }

    // ---- intra-warp redistribution of head logits (no smem, no barrier) ----
    const int mt_t   = lane >> 4;
    const int half_t = (lane >> 3) & 1;
    const int src0   = (lane & 7) * 4;
    float sigL = 0.0f, crL = 0.0f, cgL = 0.0f, cbL = 0.0f;
    #pragma unroll
    for (int mt = 0; mt < 2; mt++) {
        #pragma unroll
        for (int hf = 0; hf < 2; hf++) {
            const float v00 = __shfl_sync(0xffffffffu, hc[mt][hf * 2 + 0], src0);
            const float v01 = __shfl_sync(0xffffffffu, hc[mt][hf * 2 + 1], src0);
            const float v10 = __shfl_sync(0xffffffffu, hc[mt][hf * 2 + 0], src0 + 1);
            const float v11 = __shfl_sync(0xffffffffu, hc[mt][hf * 2 + 1], src0 + 1);
            if (mt == mt_t && hf == half_t) { sigL = v00; crL = v01; cgL = v10; cbL = v11; }
        }
    }

    // ---- per-sample nonlinearities ----
    float alpha = 0.0f, r = 0.0f, gg = 0.0f, b = 0.0f;
    if (mask) {
        const float sigma = sigL + bsig[0];
        const float tau = fmaxf(sigma, 0.0f) * step;
        alpha = 1.0f - __expf(-tau);
        r  = 1.0f / (1.0f + __expf(-(crL + brgb[0])));
        gg = 1.0f / (1.0f + __expf(-(cgL + brgb[1])));
        b  = 1.0f / (1.0f + __expf(-(cbL + brgb[2])));
    }

    // ---- composite: warp scan; pre-factors applied at combine (1 barrier) ----
    const float f = 1.0f - alpha + 1e-10f;
    float incl = f;
    #pragma unroll
    for (int off = 1; off < 32; off <<= 1) {
        const float v = __shfl_up_sync(0xffffffffu, incl, off);
        if (lane >= off) incl *= v;
    }
    const float wtot = __shfl_sync(0xffffffffu, incl, 31);
    float excl = __shfl_up_sync(0xffffffffu, incl, 1);
    if (lane == 0) excl = 1.0f;

    const float w = alpha * excl;    // warp-prefix `pre` applied at combine
    float wr = w * r, wg = w * gg, wb = w * b;
    #pragma unroll
    for (int off = 16; off > 0; off >>= 1) {
        wr += __shfl_down_sync(0xffffffffu, wr, off);
        wg += __shfl_down_sync(0xffffffffu, wg, off);
        wb += __shfl_down_sync(0xffffffffu, wb, off);
    }
    if (lane == 0) {
        sWprod[warp] = wtot;
        sSum[warp][0] = wr;
        sSum[warp][1] = wg;
        sSum[warp][2] = wb;
    }
    __syncthreads();   // barrier 2 (final combine)

    if (t == 0) {
        const float p1 = sWprod[0];
        const float p2 = p1 * sWprod[1];
        const float p3 = p2 * sWprod[2];
        const float no_hit = p3 * sWprod[3];
        out[ray * 3 + 0] = no_hit + sSum[0][0] + p1 * sSum[1][0] + p2 * sSum[2][0] + p3 * sSum[3][0];
        out[ray * 3 + 1] = no_hit + sSum[0][1] + p1 * sSum[1][1] + p2 * sSum[2][1] + p3 * sSum[3][1];
        out[ray * 3 + 2] = no_hit + sSum[0][2] + p1 * sSum[1][2] + p2 * sSum[2][2] + p3 * sSum[3][2];
    }
}

extern "C" void kernel_launch(void* const* d_in, const int* in_sizes, int n_in,
                              void* d_out, int out_size)
{
    const float* rays_o  = (const float*)d_in[0];
    const float* rays_d  = (const float*)d_in[1];
    const float* nearv   = (const float*)d_in[2];
    const float* farv    = (const float*)d_in[3];
    const float* jitter  = (const float*)d_in[4];
    const float* density = (const float*)d_in[5];
    const float* W1      = (const float*)d_in[6];
    const float* b1      = (const float*)d_in[7];
    const float* W2      = (const float*)d_in[8];
    const float* b2      = (const float*)d_in[9];
    const float* Wsig    = (const float*)d_in[10];
    const float* bsig    = (const float*)d_in[11];
    const float* Wrgb    = (const float*)d_in[12];
    const float* brgb    = (const float*)d_in[13];

    const int n_rays = in_sizes[2];   // near has one entry per ray

    pack_kernel<<<8, 128>>>(W2, Wsig, Wrgb);
    render_kernel<<<n_rays, 128>>>(rays_o, rays_d, nearv, farv, jitter, density,
                                   W1, b1, b2, bsig, brgb,
                                   (float*)d_out);
}